// round 3
// baseline (speedup 1.0000x reference)
#include <cuda_runtime.h>
#include <cuda_bf16.h>
#include <stdint.h>

// FractionalSTFT analysis:
//   k2 grid = uniform 16384 fractional frequencies (step 1/16) over the full
//   circle => W^H W = 16 * I  => pinv(W) W = I exactly (to fp32 SVD accuracy).
//   Encode->extend->decode is therefore the identity map on each frame, and
//   Hann-windowed overlap-add divided by win_norm reconstructs xp exactly;
//   cropping the reflect pad returns x itself.
// => The reference output equals the input x up to ~1e-6 reference rounding.
//    Fastest correct kernel: vectorized D2D copy of x -> out.

__global__ void fstft_copy_kernel(const float4* __restrict__ src,
                                  float4* __restrict__ dst,
                                  int n4) {
    int i = blockIdx.x * blockDim.x + threadIdx.x;
    if (i < n4) dst[i] = src[i];
}

extern "C" void kernel_launch(void* const* d_in, const int* in_sizes, int n_in,
                              void* d_out, int out_size) {
    const float* x = (const float*)d_in[0];   // (2,2,131072) float32
    float* out = (float*)d_out;               // same shape

    // out_size == b*c*l == in_sizes[0]; copy as float4 (524288 % 4 == 0)
    int n4 = out_size / 4;
    int threads = 256;
    int blocks = (n4 + threads - 1) / threads;
    fstft_copy_kernel<<<blocks, threads>>>((const float4*)x, (float4*)out, n4);

    // Handle any ragged tail defensively (out_size not multiple of 4).
    int tail = out_size - n4 * 4;
    if (tail > 0) {
        cudaMemcpyAsync(out + n4 * 4, x + n4 * 4, tail * sizeof(float),
                        cudaMemcpyDeviceToDevice);
    }
}

// round 4
// speedup vs baseline: 1.4828x; 1.4828x over previous
#include <cuda_runtime.h>
#include <cuda_bf16.h>
#include <stdint.h>

// FractionalSTFT — exact-identity reduction (verified R3: rel_err 2.7e-7):
//   The k2 grid is the uniform 16384-point fractional-frequency lattice
//   (step 1/16 over the full circle), so W^H W = 16 I and pinv(W) W = I.
//   Encode -> Hermitian-extend -> decode is the identity on each frame;
//   Hann overlap-add / win_norm reconstructs the padded signal exactly and
//   the crop returns x verbatim. Output == input.
//
// R3 showed 6.88us total with the copy kernel, ncu (cold-cache, uncontrolled
// clocks) attributing 4.8us to the kernel. True data movement floor is
// ~0.5us (4MiB through L2 at ~6.3TB/s); the remainder is graph-replay and
// node-dispatch overhead. This round: let the driver's tuned D2D memcpy be
// the single graph node — lowest possible per-replay cost for one 4MiB move.

extern "C" void kernel_launch(void* const* d_in, const int* in_sizes, int n_in,
                              void* d_out, int out_size) {
    const float* x = (const float*)d_in[0];   // (2,2,131072) float32
    float* out = (float*)d_out;

    cudaMemcpyAsync(out, x, (size_t)out_size * sizeof(float),
                    cudaMemcpyDeviceToDevice);
}